// round 15
// baseline (speedup 1.0000x reference)
#include <cuda_runtime.h>
#include <cstdint>

#define T_STEPS 4096
#define IN_DIM  512
#define H_DIM   2048
#define OUT_DIM 4

#define NCTA 128
#define COLS_PER_CTA 16
#define TPB 1024             // 32 warps: 2 warps per column
#define H4 (H_DIM/4)         // 512 float4 per column
#define IT 8                 // float4 iters per half-column
#define CIH 3                // cached iters per half (first 3 of each half)

// ---------------- device scratch (static; no allocs allowed) ----------------
__device__ float g_xz[(size_t)T_STEPS * H_DIM];
__device__ float g_xr[(size_t)T_STEPS * H_DIM];
__device__ float g_xh[(size_t)T_STEPS * H_DIM];
__device__ float g_hbuf[(size_t)(T_STEPS + 1) * H_DIM];
__device__ float g_rh[H_DIM];
__device__ float g_UzT[(size_t)H_DIM * H_DIM];
__device__ float g_UrT[(size_t)H_DIM * H_DIM];
__device__ float g_UhT[(size_t)H_DIM * H_DIM];
__device__ float g_AlT[(size_t)H_DIM * H_DIM];

// split-phase grid barrier: monotone counter + per-replay epoch
__device__ unsigned g_barCnt = 0;
__device__ unsigned g_epoch = 0;

__device__ __forceinline__ float sigm(float x) { return 1.0f / (1.0f + expf(-x)); }

#define DOT4(a, u, hv) \
    (a) = fmaf((u).x,(hv).x, fmaf((u).y,(hv).y, fmaf((u).z,(hv).z, fmaf((u).w,(hv).w,(a)))))

// ---------------- init: h0 -> g_hbuf[0] ----------------
__global__ void init_kernel(const float* __restrict__ h0) {
    int i = blockIdx.x * blockDim.x + threadIdx.x;
    if (i < H_DIM) g_hbuf[i] = h0[i];
}

// ---------------- transpose U matrices to column-major ----------------
__global__ void __launch_bounds__(256)
transpose_kernel(const float* __restrict__ Uz, const float* __restrict__ Ur,
                 const float* __restrict__ Uh, const float* __restrict__ Al) {
    __shared__ float tile[32][33];
    const int m = blockIdx.z;
    const float* src = (m == 0) ? Uz : (m == 1) ? Ur : (m == 2) ? Uh : Al;
    float* dst = (m == 0) ? g_UzT : (m == 1) ? g_UrT : (m == 2) ? g_UhT : g_AlT;
    const int x = blockIdx.x * 32 + threadIdx.x;
    const int y0 = blockIdx.y * 32;
    for (int r = threadIdx.y; r < 32; r += 8)
        tile[r][threadIdx.x] = src[(size_t)(y0 + r) * H_DIM + x];
    __syncthreads();
    const int x2 = blockIdx.y * 32 + threadIdx.x;
    const int y2 = blockIdx.x * 32;
    for (int r = threadIdx.y; r < 32; r += 8)
        dst[(size_t)(y2 + r) * H_DIM + x2] = tile[threadIdx.x][r];
}

// ---------------- input projections: x @ W_m + b_m ----------------
__global__ void __launch_bounds__(256)
xproj_kernel(const float* __restrict__ x,
             const float* __restrict__ Wz, const float* __restrict__ bz,
             const float* __restrict__ Wr, const float* __restrict__ br,
             const float* __restrict__ Wh, const float* __restrict__ bh) {
    const int mat = blockIdx.z;
    const float* W = (mat == 0) ? Wz : (mat == 1) ? Wr : Wh;
    const float* b = (mat == 0) ? bz : (mat == 1) ? br : bh;
    float* outp    = (mat == 0) ? g_xz : (mat == 1) ? g_xr : g_xh;

    const int bn = blockIdx.x * 64;
    const int bm = blockIdx.y * 64;

    __shared__ float As[16][65];
    __shared__ float Bs[16][64];

    const int tid = threadIdx.x;
    const int ty = tid >> 4, tx = tid & 15;
    const int mfrag = ty * 4, nfrag = tx * 4;

    float acc[4][4] = {};

    for (int k0 = 0; k0 < IN_DIM; k0 += 16) {
        {
            int row = tid >> 2, q = tid & 3;
            float4 v = *reinterpret_cast<const float4*>(
                x + (size_t)(bm + row) * IN_DIM + k0 + q * 4);
            As[q * 4 + 0][row] = v.x; As[q * 4 + 1][row] = v.y;
            As[q * 4 + 2][row] = v.z; As[q * 4 + 3][row] = v.w;
            int krow = tid >> 4, c4 = (tid & 15) * 4;
            float4 w = *reinterpret_cast<const float4*>(
                W + (size_t)(k0 + krow) * H_DIM + bn + c4);
            *reinterpret_cast<float4*>(&Bs[krow][c4]) = w;
        }
        __syncthreads();
        #pragma unroll
        for (int k = 0; k < 16; k++) {
            float a0 = As[k][mfrag + 0], a1 = As[k][mfrag + 1];
            float a2 = As[k][mfrag + 2], a3 = As[k][mfrag + 3];
            float4 bv = *reinterpret_cast<const float4*>(&Bs[k][nfrag]);
            acc[0][0] = fmaf(a0, bv.x, acc[0][0]); acc[0][1] = fmaf(a0, bv.y, acc[0][1]);
            acc[0][2] = fmaf(a0, bv.z, acc[0][2]); acc[0][3] = fmaf(a0, bv.w, acc[0][3]);
            acc[1][0] = fmaf(a1, bv.x, acc[1][0]); acc[1][1] = fmaf(a1, bv.y, acc[1][1]);
            acc[1][2] = fmaf(a1, bv.z, acc[1][2]); acc[1][3] = fmaf(a1, bv.w, acc[1][3]);
            acc[2][0] = fmaf(a2, bv.x, acc[2][0]); acc[2][1] = fmaf(a2, bv.y, acc[2][1]);
            acc[2][2] = fmaf(a2, bv.z, acc[2][2]); acc[2][3] = fmaf(a2, bv.w, acc[2][3]);
            acc[3][0] = fmaf(a3, bv.x, acc[3][0]); acc[3][1] = fmaf(a3, bv.y, acc[3][1]);
            acc[3][2] = fmaf(a3, bv.z, acc[3][2]); acc[3][3] = fmaf(a3, bv.w, acc[3][3]);
        }
        __syncthreads();
    }
    #pragma unroll
    for (int e = 0; e < 4; e++) {
        size_t rowoff = (size_t)(bm + mfrag + e) * H_DIM;
        #pragma unroll
        for (int f = 0; f < 4; f++) {
            int n = bn + nfrag + f;
            outp[rowoff + n] = acc[e][f] + b[n];
        }
    }
}

// ---------------- persistent scan: 2 warps/column, reg hebb halves, SMEM cache ----------------
// smem: weight cache 4 mats * 16 cols * 2 subs * CIH iters * 32 lanes * f4 (192KB)
//       | s_h 2*2048 | s_rh 2048
#define WCACHE_F4 (4 * 16 * 2 * CIH * 32)                   // 12288 float4
#define SCAN_SMEM_BYTES ((WCACHE_F4 * 4 + 3 * H_DIM) * 4)   // 221184

__global__ void __launch_bounds__(TPB, 1)
scan_kernel(const float* __restrict__ hebb0, const float* __restrict__ eta_p,
            float* __restrict__ out_hT, float* __restrict__ out_hebb) {
    extern __shared__ float smem[];
    float4* s_w4  = reinterpret_cast<float4*>(smem);        // weight cache
    float*  s_h   = smem + WCACHE_F4 * 4;                   // 2*2048 ping-pong
    float*  s_rh  = s_h + 2 * H_DIM;                        // 2048
    __shared__ float s_paz[32], s_par[32], s_ph[32], s_hnew[16];

    const int tid = threadIdx.x;
    const int w = tid >> 5;                      // warp 0..31
    const int lane = tid & 31;
    const int col = w >> 1;                      // local column 0..15
    const int sub = w & 1;                       // half: 0 = rows 0..1023, 1 = 1024..2047
    const int bid = blockIdx.x;
    const int j0 = bid * COLS_PER_CTA;
    const int j = j0 + col;

    const float eta = eta_p[0];
    const float om = 1.0f - eta;

    const unsigned ep = g_epoch;
    unsigned inst = 0;

    // fill SMEM weight cache: per half, its first CIH iters, all 4 matrices
    for (int idx = tid; idx < WCACHE_F4; idx += TPB) {
        int m   = idx / (16 * 2 * CIH * 32);
        int rem = idx % (16 * 2 * CIH * 32);
        int c   = rem / (2 * CIH * 32);
        int s   = (rem / (CIH * 32)) & 1;
        int i   = (rem / 32) % CIH;
        int l   = idx & 31;
        const float* src = (m == 0) ? g_UzT : (m == 1) ? g_UrT
                         : (m == 2) ? g_UhT : g_AlT;
        s_w4[idx] = reinterpret_cast<const float4*>(src)
                        [(size_t)(j0 + c) * H4 + (size_t)s * 256 + (size_t)i * 32 + l];
    }

    // register-resident hebb half-tile: thread owns f4 rows k = sub*256 + i*32 + lane
    float4 hb[IT];
    #pragma unroll
    for (int i = 0; i < IT; i++) {
        int r4 = 4 * (sub * 256 + i * 32 + lane);
        hb[i].x = hebb0[(size_t)(r4 + 0) * H_DIM + j];
        hb[i].y = hebb0[(size_t)(r4 + 1) * H_DIM + j];
        hb[i].z = hebb0[(size_t)(r4 + 2) * H_DIM + j];
        hb[i].w = hebb0[(size_t)(r4 + 3) * H_DIM + j];
    }

    const float4* uz4 = reinterpret_cast<const float4*>(g_UzT) + (size_t)j * H4;
    const float4* ur4 = reinterpret_cast<const float4*>(g_UrT) + (size_t)j * H4;
    const float4* uh4 = reinterpret_cast<const float4*>(g_UhT) + (size_t)j * H4;
    const float4* al4 = reinterpret_cast<const float4*>(g_AlT) + (size_t)j * H4;
    const float4* rh4 = reinterpret_cast<const float4*>(s_rh);
    const int cslot = (col * 2 + sub) * (CIH * 32);
    const float4* swz = s_w4 + (size_t)(0 * 32) * (CIH * 32) + cslot;
    const float4* swr = s_w4 + (size_t)(1 * 32) * (CIH * 32) + cslot;
    const float4* swh = s_w4 + (size_t)(2 * 32) * (CIH * 32) + cslot;
    const float4* swa = s_w4 + (size_t)(3 * 32) * (CIH * 32) + cslot;

    const int kb = sub * 256 + lane;             // this warp's f4 base row

    float hnew = 0.f;                            // h_t[j] (valid in sub0 lanes)

    for (int t = 0; t < T_STEPS; t++) {
        const int cur = t & 1;

        // early prefetch of this step's x-projections (warp-uniform broadcasts)
        const float xzv = __ldg(g_xz + (size_t)t * H_DIM + j);
        const float xrv = __ldg(g_xr + (size_t)t * H_DIM + j);
        const float xhv = __ldg(g_xh + (size_t)t * H_DIM + j);

        // ---- stage h_t ----
        {
            float2 v = __ldcg(reinterpret_cast<const float2*>(
                                  g_hbuf + (size_t)t * H_DIM) + tid);
            reinterpret_cast<float2*>(s_h + (size_t)cur * H_DIM)[tid] = v;
        }
        __syncthreads();
        const float4* h4 = reinterpret_cast<const float4*>(s_h + (size_t)cur * H_DIM);

        // ---- phase A: z/r half-dots (3 smem + 5 LDG iters) ----
        float az = 0.f, ar = 0.f;
        #pragma unroll
        for (int i = 0; i < CIH; i++) {
            float4 hv = h4[kb + i * 32];
            float4 u = swz[i * 32 + lane], v = swr[i * 32 + lane];
            DOT4(az, u, hv); DOT4(ar, v, hv);
        }
        #pragma unroll
        for (int i = CIH; i < IT; i++) {
            int k = kb + i * 32;
            float4 u = uz4[k], v = ur4[k], hv = h4[k];
            DOT4(az, u, hv); DOT4(ar, v, hv);
        }
        #pragma unroll
        for (int off = 16; off > 0; off >>= 1) {
            az += __shfl_xor_sync(0xffffffffu, az, off);
            ar += __shfl_xor_sync(0xffffffffu, ar, off);
        }
        if (lane == 0) { s_paz[w] = az; s_par[w] = ar; }
        __syncthreads();

        float z = 0.f, htj = 0.f;
        if (sub == 0) {
            float arf = xrv + s_par[2 * col] + s_par[2 * col + 1];
            float azf = xzv + s_paz[2 * col] + s_paz[2 * col + 1];
            const float r = sigm(arf);
            htj = s_h[(size_t)cur * H_DIM + j];
            if (lane == 0) g_rh[j] = r * htj;
            z = sigm(azf);
        }

        // ---- arrive B1 ----
        __syncthreads();
        if (tid == 0) { __threadfence(); atomicAdd(&g_barCnt, 1u); }
        // ---- B1 shadow: sub1 completes hebb_t bottom half (rows 1024..2047) ----
        if (t > 0 && sub == 1) {
            const float4* hm4 = reinterpret_cast<const float4*>(
                s_h + (size_t)(cur ^ 1) * H_DIM);    // h_{t-1}
            const float eh = eta * s_h[(size_t)cur * H_DIM + j];   // eta * h_t[j]
            #pragma unroll
            for (int i = 0; i < IT; i++) {
                float4 hm = hm4[kb + i * 32];
                hb[i].x = fmaf(om, hb[i].x, eh * hm.x);
                hb[i].y = fmaf(om, hb[i].y, eh * hm.y);
                hb[i].z = fmaf(om, hb[i].z, eh * hm.z);
                hb[i].w = fmaf(om, hb[i].w, eh * hm.w);
            }
        }
        // ---- wait B1 ----
        {
            unsigned target = ep + (++inst) * NCTA;
            if (tid == 0) {
                while ((int)(*(volatile unsigned*)&g_barCnt - target) < 0)
                    __nanosleep(32);
            }
            __syncthreads();
        }

        // ---- stage rh ----
        {
            float2 v = __ldcg(reinterpret_cast<const float2*>(g_rh) + tid);
            reinterpret_cast<float2*>(s_rh)[tid] = v;
        }
        __syncthreads();

        // ---- phase B: half-dot rh . (Uh + alpha*hebb_t) ----
        float acc = 0.f;
        #pragma unroll
        for (int i = 0; i < CIH; i++) {
            int k = kb + i * 32;
            float4 rr = rh4[k];
            float4 U = swh[i * 32 + lane], A = swa[i * 32 + lane];
            acc = fmaf(rr.x, fmaf(A.x, hb[i].x, U.x), acc);
            acc = fmaf(rr.y, fmaf(A.y, hb[i].y, U.y), acc);
            acc = fmaf(rr.z, fmaf(A.z, hb[i].z, U.z), acc);
            acc = fmaf(rr.w, fmaf(A.w, hb[i].w, U.w), acc);
        }
        #pragma unroll
        for (int i = CIH; i < IT; i++) {
            int k = kb + i * 32;
            float4 rr = rh4[k];
            float4 U = uh4[k], A = al4[k];
            acc = fmaf(rr.x, fmaf(A.x, hb[i].x, U.x), acc);
            acc = fmaf(rr.y, fmaf(A.y, hb[i].y, U.y), acc);
            acc = fmaf(rr.z, fmaf(A.z, hb[i].z, U.z), acc);
            acc = fmaf(rr.w, fmaf(A.w, hb[i].w, U.w), acc);
        }
        #pragma unroll
        for (int off = 16; off > 0; off >>= 1)
            acc += __shfl_xor_sync(0xffffffffu, acc, off);
        if (lane == 0) s_ph[w] = acc;
        __syncthreads();

        if (sub == 0) {
            float accf = s_ph[2 * col] + s_ph[2 * col + 1];
            float htil = tanhf(xhv + accf);
            hnew = (1.0f - z) * htj + z * htil;  // all sub0 lanes hold h_{t+1}[j]
            if (lane == 0) {
                g_hbuf[(size_t)(t + 1) * H_DIM + j] = hnew;
                s_hnew[col] = hnew;
            }
        }

        // ---- arrive B2 ----
        __syncthreads();
        if (tid == 0) { __threadfence(); atomicAdd(&g_barCnt, 1u); }
        // ---- B2 shadow: sub0 starts hebb_{t+1} top half (rows 0..1023) ----
        if (sub == 0) {
            const float eh = eta * hnew;
            #pragma unroll
            for (int i = 0; i < IT; i++) {
                float4 ht = h4[kb + i * 32];         // h_t
                hb[i].x = fmaf(om, hb[i].x, eh * ht.x);
                hb[i].y = fmaf(om, hb[i].y, eh * ht.y);
                hb[i].z = fmaf(om, hb[i].z, eh * ht.z);
                hb[i].w = fmaf(om, hb[i].w, eh * ht.w);
            }
        }
        // ---- wait B2 ----
        {
            unsigned target = ep + (++inst) * NCTA;
            if (tid == 0) {
                while ((int)(*(volatile unsigned*)&g_barCnt - target) < 0)
                    __nanosleep(32);
            }
            __syncthreads();
        }
    }

    // ---- finalize: sub1 completes hebb_T bottom half (h_{T-1} in s_h[1]) ----
    if (sub == 1) {
        const float4* hm4 = reinterpret_cast<const float4*>(s_h + H_DIM);
        const float eh = eta * s_hnew[col];          // eta * h_T[j]
        #pragma unroll
        for (int i = 0; i < IT; i++) {
            float4 hm = hm4[kb + i * 32];
            hb[i].x = fmaf(om, hb[i].x, eh * hm.x);
            hb[i].y = fmaf(om, hb[i].y, eh * hm.y);
            hb[i].z = fmaf(om, hb[i].z, eh * hm.z);
            hb[i].w = fmaf(om, hb[i].w, eh * hm.w);
        }
    }
    if (sub == 0 && lane == 0) out_hT[j] = hnew;

    // dump hebb regs into (now dead) weight-cache SMEM, col-major [16][2048]
    __syncthreads();
    float* s_tmp = smem;
    #pragma unroll
    for (int i = 0; i < IT; i++) {
        int k = kb + i * 32;
        *reinterpret_cast<float4*>(&s_tmp[(size_t)col * H_DIM + 4 * k]) = hb[i];
    }
    __syncthreads();
    // cooperative transposed write-out
    for (int i = tid; i < H_DIM; i += TPB) {
        float tmp[16];
        #pragma unroll
        for (int c = 0; c < 16; c++) tmp[c] = s_tmp[(size_t)c * H_DIM + i];
        float4* dst = reinterpret_cast<float4*>(out_hebb + (size_t)i * H_DIM + j0);
        dst[0] = make_float4(tmp[0], tmp[1], tmp[2], tmp[3]);
        dst[1] = make_float4(tmp[4], tmp[5], tmp[6], tmp[7]);
        dst[2] = make_float4(tmp[8], tmp[9], tmp[10], tmp[11]);
        dst[3] = make_float4(tmp[12], tmp[13], tmp[14], tmp[15]);
    }
    // advance epoch for next graph replay
    if (bid == 0 && tid == 0) g_epoch = ep + 2u * T_STEPS * NCTA;
}

// ---------------- output projection: y @ Wo + bo ----------------
__global__ void __launch_bounds__(256)
out_gemm_kernel(const float* __restrict__ Wo, const float* __restrict__ bo,
                float* __restrict__ out) {
    const int t = blockIdx.x;
    const int tid = threadIdx.x;
    const float* y = g_hbuf + (size_t)(t + 1) * H_DIM;
    float a0 = 0.f, a1 = 0.f, a2 = 0.f, a3 = 0.f;
    for (int jj = tid; jj < H_DIM; jj += 256) {
        float hv = y[jj];
        float4 w = *reinterpret_cast<const float4*>(Wo + (size_t)jj * OUT_DIM);
        a0 = fmaf(hv, w.x, a0); a1 = fmaf(hv, w.y, a1);
        a2 = fmaf(hv, w.z, a2); a3 = fmaf(hv, w.w, a3);
    }
    #pragma unroll
    for (int off = 16; off > 0; off >>= 1) {
        a0 += __shfl_down_sync(0xffffffffu, a0, off);
        a1 += __shfl_down_sync(0xffffffffu, a1, off);
        a2 += __shfl_down_sync(0xffffffffu, a2, off);
        a3 += __shfl_down_sync(0xffffffffu, a3, off);
    }
    __shared__ float red[8][4];
    const int wid = tid >> 5, lane = tid & 31;
    if (lane == 0) { red[wid][0] = a0; red[wid][1] = a1; red[wid][2] = a2; red[wid][3] = a3; }
    __syncthreads();
    if (tid < OUT_DIM) {
        float s = bo[tid];
        #pragma unroll
        for (int w = 0; w < 8; w++) s += red[w][tid];
        out[(size_t)t * OUT_DIM + tid] = s;
    }
}

// ---------------- JAX threefry2x32 (partitionable) / fold_in / categorical ----------------
__device__ __forceinline__ uint32_t rotl32(uint32_t x, int r) {
    return (x << r) | (x >> (32 - r));
}

__device__ __forceinline__ void threefry2x32(uint32_t k0, uint32_t k1,
                                             uint32_t x0, uint32_t x1,
                                             uint32_t& o0, uint32_t& o1) {
    uint32_t ks2 = k0 ^ k1 ^ 0x1BD11BDAu;
    uint32_t ks[3] = {k0, k1, ks2};
    const int r0[4] = {13, 15, 26, 6};
    const int r1[4] = {17, 29, 16, 24};
    x0 += k0; x1 += k1;
    #pragma unroll
    for (int d = 0; d < 5; d++) {
        const int* rr = (d & 1) ? r1 : r0;
        #pragma unroll
        for (int qv = 0; qv < 4; qv++) { x0 += x1; x1 = rotl32(x1, rr[qv]); x1 ^= x0; }
        x0 += ks[(d + 1) % 3];
        x1 += ks[(d + 2) % 3] + (uint32_t)(d + 1);
    }
    o0 = x0; o1 = x1;
}

__device__ __forceinline__ float gumbel_from_bits(uint32_t bits) {
    float f = __uint_as_float((bits >> 9) | 0x3f800000u) - 1.0f;
    const float tiny = 1.17549435e-38f;
    float u = f * (1.0f - tiny) + tiny;
    u = fmaxf(tiny, u);
    return -logf(-logf(u));
}

__global__ void action_kernel(const float* __restrict__ logits,
                              float* __restrict__ act_out,
                              const int* __restrict__ seed_p) {
    int t = blockIdx.x * blockDim.x + threadIdx.x;
    if (t >= T_STEPS) return;
    int seed = seed_p[0];
    uint32_t k0 = (seed < 0) ? 0xFFFFFFFFu : 0u;
    uint32_t k1 = (uint32_t)seed;
    uint32_t fk0, fk1;
    threefry2x32(k0, k1, 0u, 1u, fk0, fk1);        // fold_in(key, 1)

    uint32_t b[2];
    #pragma unroll
    for (int c = 0; c < 2; c++) {
        uint32_t m = 2u * (uint32_t)t + (uint32_t)c;
        uint32_t o0, o1;
        threefry2x32(fk0, fk1, 0u, m, o0, o1);
        b[c] = o0 ^ o1;
    }
    float v0 = logits[(size_t)t * OUT_DIM + 0] + gumbel_from_bits(b[0]);
    float v1 = logits[(size_t)t * OUT_DIM + 1] + gumbel_from_bits(b[1]);
    act_out[t] = (v1 > v0) ? 1.0f : 0.0f;
}

// ---------------- launch ----------------
extern "C" void kernel_launch(void* const* d_in, const int* in_sizes, int n_in,
                              void* d_out, int out_size) {
    const float* x     = (const float*)d_in[0];
    const float* h0    = (const float*)d_in[1];
    const float* hebb0 = (const float*)d_in[2];
    const float* Wz    = (const float*)d_in[3];
    const float* Uz    = (const float*)d_in[4];
    const float* bz    = (const float*)d_in[5];
    const float* Wr    = (const float*)d_in[6];
    const float* Ur    = (const float*)d_in[7];
    const float* br    = (const float*)d_in[8];
    const float* Wh    = (const float*)d_in[9];
    const float* Uh    = (const float*)d_in[10];
    const float* bh    = (const float*)d_in[11];
    const float* alpha = (const float*)d_in[12];
    const float* eta   = (const float*)d_in[13];
    const float* Wo    = (const float*)d_in[14];
    const float* bo    = (const float*)d_in[15];
    const int*   seed  = (const int*)d_in[16];
    float* out = (float*)d_out;

    float* out_output = out;
    float* out_action = out + (size_t)T_STEPS * OUT_DIM;
    float* out_hT     = out_action + T_STEPS;
    float* out_hebb   = out_hT + H_DIM;

    cudaFuncSetAttribute(scan_kernel,
                         cudaFuncAttributeMaxDynamicSharedMemorySize,
                         SCAN_SMEM_BYTES);

    init_kernel<<<(H_DIM + 255) / 256, 256>>>(h0);

    dim3 gtr(H_DIM / 32, H_DIM / 32, 4);
    transpose_kernel<<<gtr, dim3(32, 8)>>>(Uz, Ur, Uh, alpha);

    dim3 gproj(H_DIM / 64, T_STEPS / 64, 3);
    xproj_kernel<<<gproj, 256>>>(x, Wz, bz, Wr, br, Wh, bh);

    scan_kernel<<<NCTA, TPB, SCAN_SMEM_BYTES>>>(hebb0, eta, out_hT, out_hebb);

    out_gemm_kernel<<<T_STEPS, 256>>>(Wo, bo, out_output);

    action_kernel<<<(T_STEPS + 255) / 256, 256>>>(out_output, out_action, seed);
}

// round 16
// speedup vs baseline: 1.1867x; 1.1867x over previous
#include <cuda_runtime.h>
#include <cstdint>

#define T_STEPS 4096
#define IN_DIM  512
#define H_DIM   2048
#define OUT_DIM 4

#define NCTA 128
#define COLS_PER_CTA 16
#define TPB 512              // 16 warps: one warp per column
#define H4 (H_DIM/4)         // 512 float4 per column
#define CI 6                 // weight iters cached in SMEM (0..CI-1)

// ---------------- device scratch (static; no allocs allowed) ----------------
__device__ float g_xz[(size_t)T_STEPS * H_DIM];
__device__ float g_xr[(size_t)T_STEPS * H_DIM];
__device__ float g_xh[(size_t)T_STEPS * H_DIM];
__device__ float g_hbuf[(size_t)(T_STEPS + 1) * H_DIM];
__device__ float g_rh[H_DIM];
__device__ float g_UzT[(size_t)H_DIM * H_DIM];
__device__ float g_UrT[(size_t)H_DIM * H_DIM];
__device__ float g_UhT[(size_t)H_DIM * H_DIM];
__device__ float g_AlT[(size_t)H_DIM * H_DIM];

// split-phase grid barrier: monotone counter + per-replay epoch
__device__ unsigned g_barCnt = 0;
__device__ unsigned g_epoch = 0;

__device__ __forceinline__ float sigm(float x) { return 1.0f / (1.0f + expf(-x)); }

#define DOT4(a, u, hv) \
    (a) = fmaf((u).x,(hv).x, fmaf((u).y,(hv).y, fmaf((u).z,(hv).z, fmaf((u).w,(hv).w,(a)))))

// ---------------- init: h0 -> g_hbuf[0] ----------------
__global__ void init_kernel(const float* __restrict__ h0) {
    int i = blockIdx.x * blockDim.x + threadIdx.x;
    if (i < H_DIM) g_hbuf[i] = h0[i];
}

// ---------------- transpose U matrices to column-major ----------------
__global__ void __launch_bounds__(256)
transpose_kernel(const float* __restrict__ Uz, const float* __restrict__ Ur,
                 const float* __restrict__ Uh, const float* __restrict__ Al) {
    __shared__ float tile[32][33];
    const int m = blockIdx.z;
    const float* src = (m == 0) ? Uz : (m == 1) ? Ur : (m == 2) ? Uh : Al;
    float* dst = (m == 0) ? g_UzT : (m == 1) ? g_UrT : (m == 2) ? g_UhT : g_AlT;
    const int x = blockIdx.x * 32 + threadIdx.x;
    const int y0 = blockIdx.y * 32;
    for (int r = threadIdx.y; r < 32; r += 8)
        tile[r][threadIdx.x] = src[(size_t)(y0 + r) * H_DIM + x];
    __syncthreads();
    const int x2 = blockIdx.y * 32 + threadIdx.x;
    const int y2 = blockIdx.x * 32;
    for (int r = threadIdx.y; r < 32; r += 8)
        dst[(size_t)(y2 + r) * H_DIM + x2] = tile[threadIdx.x][r];
}

// ---------------- input projections: x @ W_m + b_m ----------------
__global__ void __launch_bounds__(256)
xproj_kernel(const float* __restrict__ x,
             const float* __restrict__ Wz, const float* __restrict__ bz,
             const float* __restrict__ Wr, const float* __restrict__ br,
             const float* __restrict__ Wh, const float* __restrict__ bh) {
    const int mat = blockIdx.z;
    const float* W = (mat == 0) ? Wz : (mat == 1) ? Wr : Wh;
    const float* b = (mat == 0) ? bz : (mat == 1) ? br : bh;
    float* outp    = (mat == 0) ? g_xz : (mat == 1) ? g_xr : g_xh;

    const int bn = blockIdx.x * 64;
    const int bm = blockIdx.y * 64;

    __shared__ float As[16][65];
    __shared__ float Bs[16][64];

    const int tid = threadIdx.x;
    const int ty = tid >> 4, tx = tid & 15;
    const int mfrag = ty * 4, nfrag = tx * 4;

    float acc[4][4] = {};

    for (int k0 = 0; k0 < IN_DIM; k0 += 16) {
        {
            int row = tid >> 2, q = tid & 3;
            float4 v = *reinterpret_cast<const float4*>(
                x + (size_t)(bm + row) * IN_DIM + k0 + q * 4);
            As[q * 4 + 0][row] = v.x; As[q * 4 + 1][row] = v.y;
            As[q * 4 + 2][row] = v.z; As[q * 4 + 3][row] = v.w;
            int krow = tid >> 4, c4 = (tid & 15) * 4;
            float4 w = *reinterpret_cast<const float4*>(
                W + (size_t)(k0 + krow) * H_DIM + bn + c4);
            *reinterpret_cast<float4*>(&Bs[krow][c4]) = w;
        }
        __syncthreads();
        #pragma unroll
        for (int k = 0; k < 16; k++) {
            float a0 = As[k][mfrag + 0], a1 = As[k][mfrag + 1];
            float a2 = As[k][mfrag + 2], a3 = As[k][mfrag + 3];
            float4 bv = *reinterpret_cast<const float4*>(&Bs[k][nfrag]);
            acc[0][0] = fmaf(a0, bv.x, acc[0][0]); acc[0][1] = fmaf(a0, bv.y, acc[0][1]);
            acc[0][2] = fmaf(a0, bv.z, acc[0][2]); acc[0][3] = fmaf(a0, bv.w, acc[0][3]);
            acc[1][0] = fmaf(a1, bv.x, acc[1][0]); acc[1][1] = fmaf(a1, bv.y, acc[1][1]);
            acc[1][2] = fmaf(a1, bv.z, acc[1][2]); acc[1][3] = fmaf(a1, bv.w, acc[1][3]);
            acc[2][0] = fmaf(a2, bv.x, acc[2][0]); acc[2][1] = fmaf(a2, bv.y, acc[2][1]);
            acc[2][2] = fmaf(a2, bv.z, acc[2][2]); acc[2][3] = fmaf(a2, bv.w, acc[2][3]);
            acc[3][0] = fmaf(a3, bv.x, acc[3][0]); acc[3][1] = fmaf(a3, bv.y, acc[3][1]);
            acc[3][2] = fmaf(a3, bv.z, acc[3][2]); acc[3][3] = fmaf(a3, bv.w, acc[3][3]);
        }
        __syncthreads();
    }
    #pragma unroll
    for (int e = 0; e < 4; e++) {
        size_t rowoff = (size_t)(bm + mfrag + e) * H_DIM;
        #pragma unroll
        for (int f = 0; f < 4; f++) {
            int n = bn + nfrag + f;
            outp[rowoff + n] = acc[e][f] + b[n];
        }
    }
}

// ---------------- persistent scan: register hebb + SMEM weight cache
//                  + x prefetch (R14) + extra cached Uh iter (R16) ----------------
// smem: weight cache 4 mats * 16 cols * CI iters * 32 lanes * float4
//       + Uh iter-6 extension 16 cols * 32 lanes * float4 (8KB)
//       | s_h 2*2048 | s_rh 2048
#define WCACHE_F4 (4 * 16 * CI * 32)                       // 12288 float4
#define UH7_F4    (16 * 32)                                // 512 float4
#define SCAN_SMEM_BYTES (((WCACHE_F4 + UH7_F4) * 4 + 3 * H_DIM) * 4)  // 229376

__global__ void __launch_bounds__(TPB, 1)
scan_kernel(const float* __restrict__ hebb0, const float* __restrict__ eta_p,
            float* __restrict__ out_hT, float* __restrict__ out_hebb) {
    extern __shared__ float smem[];
    float4* s_w4  = reinterpret_cast<float4*>(smem);       // weight cache
    float4* s_uh7 = s_w4 + WCACHE_F4;                      // Uh iter 6
    float*  s_h   = smem + (WCACHE_F4 + UH7_F4) * 4;       // 2*2048 ping-pong
    float*  s_rh  = s_h + 2 * H_DIM;                       // 2048

    const int tid = threadIdx.x;
    const int w = tid >> 5;                     // warp = local column 0..15
    const int lane = tid & 31;
    const int bid = blockIdx.x;
    const int j0 = bid * COLS_PER_CTA;
    const int j = j0 + w;

    const float eta = eta_p[0];
    const float om = 1.0f - eta;

    const unsigned ep = g_epoch;
    unsigned inst = 0;

    // fill SMEM weight cache: iters 0..CI-1 of all 4 matrices
    for (int idx = tid; idx < WCACHE_F4; idx += TPB) {
        int m   = idx / (16 * CI * 32);
        int rem = idx % (16 * CI * 32);
        int c   = rem / (CI * 32);
        int i   = (rem / 32) % CI;
        int l   = idx & 31;
        const float* src = (m == 0) ? g_UzT : (m == 1) ? g_UrT
                         : (m == 2) ? g_UhT : g_AlT;
        s_w4[idx] = reinterpret_cast<const float4*>(src)
                        [(size_t)(j0 + c) * H4 + (size_t)i * 32 + l];
    }
    // fill Uh iter-6 extension
    for (int idx = tid; idx < UH7_F4; idx += TPB) {
        int c = idx >> 5, l = idx & 31;
        s_uh7[idx] = reinterpret_cast<const float4*>(g_UhT)
                         [(size_t)(j0 + c) * H4 + (size_t)CI * 32 + l];
    }

    // register-resident hebb tile: thread (w,lane) owns rows 4*(lane+i*32)..+3 of col j
    float4 hb[16];
    #pragma unroll
    for (int i = 0; i < 16; i++) {
        int r4 = 4 * (lane + i * 32);
        hb[i].x = hebb0[(size_t)(r4 + 0) * H_DIM + j];
        hb[i].y = hebb0[(size_t)(r4 + 1) * H_DIM + j];
        hb[i].z = hebb0[(size_t)(r4 + 2) * H_DIM + j];
        hb[i].w = hebb0[(size_t)(r4 + 3) * H_DIM + j];
    }

    const float4* uz4 = reinterpret_cast<const float4*>(g_UzT) + (size_t)j * H4;
    const float4* ur4 = reinterpret_cast<const float4*>(g_UrT) + (size_t)j * H4;
    const float4* uh4 = reinterpret_cast<const float4*>(g_UhT) + (size_t)j * H4;
    const float4* al4 = reinterpret_cast<const float4*>(g_AlT) + (size_t)j * H4;
    const float4* rh4 = reinterpret_cast<const float4*>(s_rh);
    const float4* swz = s_w4 + (size_t)(0 * 16 + w) * (CI * 32);
    const float4* swr = s_w4 + (size_t)(1 * 16 + w) * (CI * 32);
    const float4* swh = s_w4 + (size_t)(2 * 16 + w) * (CI * 32);
    const float4* swa = s_w4 + (size_t)(3 * 16 + w) * (CI * 32);
    const float4* suh7 = s_uh7 + (size_t)w * 32;

    float hnew = 0.f;   // h_t[j], carried across steps

    for (int t = 0; t < T_STEPS; t++) {
        const int cur = t & 1;

        // ---- early prefetch of this step's x-projections (off the critical path) ----
        const float xzv = __ldg(g_xz + (size_t)t * H_DIM + j);
        const float xrv = __ldg(g_xr + (size_t)t * H_DIM + j);
        const float xhv = __ldg(g_xh + (size_t)t * H_DIM + j);

        // ---- stage h_t ----
        {
            float4 v = __ldcg(reinterpret_cast<const float4*>(
                                  g_hbuf + (size_t)t * H_DIM) + tid);
            reinterpret_cast<float4*>(s_h + (size_t)cur * H_DIM)[tid] = v;
        }
        __syncthreads();
        const float4* h4 = reinterpret_cast<const float4*>(s_h + (size_t)cur * H_DIM);

        // ---- phase A: z/r dots (iters 0..CI-1 smem, rest LDG) ----
        float az = 0.f, ar = 0.f;
        #pragma unroll
        for (int i = 0; i < CI; i++) {
            float4 hv = h4[lane + i * 32];
            float4 u = swz[i * 32 + lane], v = swr[i * 32 + lane];
            DOT4(az, u, hv); DOT4(ar, v, hv);
        }
        #pragma unroll
        for (int i = CI; i < 16; i++) {
            int k = lane + i * 32;
            float4 u = uz4[k], v = ur4[k], hv = h4[k];
            DOT4(az, u, hv); DOT4(ar, v, hv);
        }
        #pragma unroll
        for (int off = 16; off > 0; off >>= 1) {
            az += __shfl_xor_sync(0xffffffffu, az, off);
            ar += __shfl_xor_sync(0xffffffffu, ar, off);
        }
        // publish rh FIRST (other CTAs wait on it), then compute z locally
        const float r = sigm(xrv + ar);
        const float htj = s_h[(size_t)cur * H_DIM + j];
        if (lane == 0) g_rh[j] = r * htj;
        const float z = sigm(xzv + az);

        // ---- arrive B1 ----
        __syncthreads();
        if (tid == 0) { __threadfence(); atomicAdd(&g_barCnt, 1u); }
        // ---- B1 shadow: second half of hebb_t update (rows 1024..2047), regs ----
        if (t > 0) {
            const float4* hm4 = reinterpret_cast<const float4*>(
                s_h + (size_t)(cur ^ 1) * H_DIM);   // h_{t-1}
            const float eh = eta * hnew;            // hnew == h_t[j]
            #pragma unroll
            for (int i = 8; i < 16; i++) {
                float4 hm = hm4[lane + i * 32];
                hb[i].x = fmaf(om, hb[i].x, eh * hm.x);
                hb[i].y = fmaf(om, hb[i].y, eh * hm.y);
                hb[i].z = fmaf(om, hb[i].z, eh * hm.z);
                hb[i].w = fmaf(om, hb[i].w, eh * hm.w);
            }
        }
        // ---- wait B1 ----
        {
            unsigned target = ep + (++inst) * NCTA;
            if (tid == 0) {
                while ((int)(*(volatile unsigned*)&g_barCnt - target) < 0)
                    __nanosleep(32);
            }
            __syncthreads();
        }

        // ---- stage rh ----
        {
            float4 v = __ldcg(reinterpret_cast<const float4*>(g_rh) + tid);
            reinterpret_cast<float4*>(s_rh)[tid] = v;
        }
        __syncthreads();

        // ---- phase B: pure dot rh . (Uh + alpha*hebb_t), hebb in regs ----
        float acc = 0.f;
        #pragma unroll
        for (int i = 0; i < CI; i++) {
            float4 rr = rh4[lane + i * 32];
            float4 U = swh[i * 32 + lane], A = swa[i * 32 + lane];
            acc = fmaf(rr.x, fmaf(A.x, hb[i].x, U.x), acc);
            acc = fmaf(rr.y, fmaf(A.y, hb[i].y, U.y), acc);
            acc = fmaf(rr.z, fmaf(A.z, hb[i].z, U.z), acc);
            acc = fmaf(rr.w, fmaf(A.w, hb[i].w, U.w), acc);
        }
        {   // iter CI (= 6): Uh cached in SMEM extension, alpha streamed
            int k = lane + CI * 32;
            float4 rr = rh4[k];
            float4 U = suh7[lane], A = al4[k];
            acc = fmaf(rr.x, fmaf(A.x, hb[CI].x, U.x), acc);
            acc = fmaf(rr.y, fmaf(A.y, hb[CI].y, U.y), acc);
            acc = fmaf(rr.z, fmaf(A.z, hb[CI].z, U.z), acc);
            acc = fmaf(rr.w, fmaf(A.w, hb[CI].w, U.w), acc);
        }
        #pragma unroll
        for (int i = CI + 1; i < 16; i++) {
            int k = lane + i * 32;
            float4 rr = rh4[k];
            float4 U = uh4[k], A = al4[k];
            acc = fmaf(rr.x, fmaf(A.x, hb[i].x, U.x), acc);
            acc = fmaf(rr.y, fmaf(A.y, hb[i].y, U.y), acc);
            acc = fmaf(rr.z, fmaf(A.z, hb[i].z, U.z), acc);
            acc = fmaf(rr.w, fmaf(A.w, hb[i].w, U.w), acc);
        }
        #pragma unroll
        for (int off = 16; off > 0; off >>= 1)
            acc += __shfl_xor_sync(0xffffffffu, acc, off);

        const float htil = tanhf(xhv + acc);
        const float hnew_t = (1.0f - z) * htj + z * htil;
        if (lane == 0) g_hbuf[(size_t)(t + 1) * H_DIM + j] = hnew_t;

        // ---- arrive B2 ----
        __syncthreads();
        if (tid == 0) { __threadfence(); atomicAdd(&g_barCnt, 1u); }
        // ---- B2 shadow: first half of hebb_{t+1} update (rows 0..1023), regs ----
        {
            const float eh = eta * hnew_t;
            #pragma unroll
            for (int i = 0; i < 8; i++) {
                float4 ht = h4[lane + i * 32];      // h_t
                hb[i].x = fmaf(om, hb[i].x, eh * ht.x);
                hb[i].y = fmaf(om, hb[i].y, eh * ht.y);
                hb[i].z = fmaf(om, hb[i].z, eh * ht.z);
                hb[i].w = fmaf(om, hb[i].w, eh * ht.w);
            }
        }
        hnew = hnew_t;
        // ---- wait B2 ----
        {
            unsigned target = ep + (++inst) * NCTA;
            if (tid == 0) {
                while ((int)(*(volatile unsigned*)&g_barCnt - target) < 0)
                    __nanosleep(32);
            }
            __syncthreads();
        }
    }

    // ---- finalize: second half of hebb_T update (h_{T-1} in s_h[1]) ----
    {
        const float4* hm4 = reinterpret_cast<const float4*>(s_h + H_DIM);
        const float eh = eta * hnew;                // h_T[j]
        #pragma unroll
        for (int i = 8; i < 16; i++) {
            float4 hm = hm4[lane + i * 32];
            hb[i].x = fmaf(om, hb[i].x, eh * hm.x);
            hb[i].y = fmaf(om, hb[i].y, eh * hm.y);
            hb[i].z = fmaf(om, hb[i].z, eh * hm.z);
            hb[i].w = fmaf(om, hb[i].w, eh * hm.w);
        }
    }
    if (lane == 0) out_hT[j] = hnew;

    // dump hebb regs into (now dead) weight-cache SMEM, col-major [16][2048]
    __syncthreads();
    float* s_tmp = smem;
    #pragma unroll
    for (int i = 0; i < 16; i++) {
        int k = lane + i * 32;
        *reinterpret_cast<float4*>(&s_tmp[(size_t)w * H_DIM + 4 * k]) = hb[i];
    }
    __syncthreads();
    // cooperative transposed write-out
    for (int i = tid; i < H_DIM; i += TPB) {
        float tmp[16];
        #pragma unroll
        for (int c = 0; c < 16; c++) tmp[c] = s_tmp[(size_t)c * H_DIM + i];
        float4* dst = reinterpret_cast<float4*>(out_hebb + (size_t)i * H_DIM + j0);
        dst[0] = make_float4(tmp[0], tmp[1], tmp[2], tmp[3]);
        dst[1] = make_float4(tmp[4], tmp[5], tmp[6], tmp[7]);
        dst[2] = make_float4(tmp[8], tmp[9], tmp[10], tmp[11]);
        dst[3] = make_float4(tmp[12], tmp[13], tmp[14], tmp[15]);
    }
    // advance epoch for next graph replay
    if (bid == 0 && tid == 0) g_epoch = ep + 2u * T_STEPS * NCTA;
}

// ---------------- output projection: y @ Wo + bo ----------------
__global__ void __launch_bounds__(256)
out_gemm_kernel(const float* __restrict__ Wo, const float* __restrict__ bo,
                float* __restrict__ out) {
    const int t = blockIdx.x;
    const int tid = threadIdx.x;
    const float* y = g_hbuf + (size_t)(t + 1) * H_DIM;
    float a0 = 0.f, a1 = 0.f, a2 = 0.f, a3 = 0.f;
    for (int jj = tid; jj < H_DIM; jj += 256) {
        float hv = y[jj];
        float4 w = *reinterpret_cast<const float4*>(Wo + (size_t)jj * OUT_DIM);
        a0 = fmaf(hv, w.x, a0); a1 = fmaf(hv, w.y, a1);
        a2 = fmaf(hv, w.z, a2); a3 = fmaf(hv, w.w, a3);
    }
    #pragma unroll
    for (int off = 16; off > 0; off >>= 1) {
        a0 += __shfl_down_sync(0xffffffffu, a0, off);
        a1 += __shfl_down_sync(0xffffffffu, a1, off);
        a2 += __shfl_down_sync(0xffffffffu, a2, off);
        a3 += __shfl_down_sync(0xffffffffu, a3, off);
    }
    __shared__ float red[8][4];
    const int wid = tid >> 5, lane = tid & 31;
    if (lane == 0) { red[wid][0] = a0; red[wid][1] = a1; red[wid][2] = a2; red[wid][3] = a3; }
    __syncthreads();
    if (tid < OUT_DIM) {
        float s = bo[tid];
        #pragma unroll
        for (int w = 0; w < 8; w++) s += red[w][tid];
        out[(size_t)t * OUT_DIM + tid] = s;
    }
}

// ---------------- JAX threefry2x32 (partitionable) / fold_in / categorical ----------------
__device__ __forceinline__ uint32_t rotl32(uint32_t x, int r) {
    return (x << r) | (x >> (32 - r));
}

__device__ __forceinline__ void threefry2x32(uint32_t k0, uint32_t k1,
                                             uint32_t x0, uint32_t x1,
                                             uint32_t& o0, uint32_t& o1) {
    uint32_t ks2 = k0 ^ k1 ^ 0x1BD11BDAu;
    uint32_t ks[3] = {k0, k1, ks2};
    const int r0[4] = {13, 15, 26, 6};
    const int r1[4] = {17, 29, 16, 24};
    x0 += k0; x1 += k1;
    #pragma unroll
    for (int d = 0; d < 5; d++) {
        const int* rr = (d & 1) ? r1 : r0;
        #pragma unroll
        for (int qv = 0; qv < 4; qv++) { x0 += x1; x1 = rotl32(x1, rr[qv]); x1 ^= x0; }
        x0 += ks[(d + 1) % 3];
        x1 += ks[(d + 2) % 3] + (uint32_t)(d + 1);
    }
    o0 = x0; o1 = x1;
}

__device__ __forceinline__ float gumbel_from_bits(uint32_t bits) {
    float f = __uint_as_float((bits >> 9) | 0x3f800000u) - 1.0f;
    const float tiny = 1.17549435e-38f;
    float u = f * (1.0f - tiny) + tiny;
    u = fmaxf(tiny, u);
    return -logf(-logf(u));
}

__global__ void action_kernel(const float* __restrict__ logits,
                              float* __restrict__ act_out,
                              const int* __restrict__ seed_p) {
    int t = blockIdx.x * blockDim.x + threadIdx.x;
    if (t >= T_STEPS) return;
    int seed = seed_p[0];
    uint32_t k0 = (seed < 0) ? 0xFFFFFFFFu : 0u;
    uint32_t k1 = (uint32_t)seed;
    uint32_t fk0, fk1;
    threefry2x32(k0, k1, 0u, 1u, fk0, fk1);        // fold_in(key, 1)

    uint32_t b[2];
    #pragma unroll
    for (int c = 0; c < 2; c++) {
        uint32_t m = 2u * (uint32_t)t + (uint32_t)c;
        uint32_t o0, o1;
        threefry2x32(fk0, fk1, 0u, m, o0, o1);
        b[c] = o0 ^ o1;
    }
    float v0 = logits[(size_t)t * OUT_DIM + 0] + gumbel_from_bits(b[0]);
    float v1 = logits[(size_t)t * OUT_DIM + 1] + gumbel_from_bits(b[1]);
    act_out[t] = (v1 > v0) ? 1.0f : 0.0f;
}

// ---------------- launch ----------------
extern "C" void kernel_launch(void* const* d_in, const int* in_sizes, int n_in,
                              void* d_out, int out_size) {
    const float* x     = (const float*)d_in[0];
    const float* h0    = (const float*)d_in[1];
    const float* hebb0 = (const float*)d_in[2];
    const float* Wz    = (const float*)d_in[3];
    const float* Uz    = (const float*)d_in[4];
    const float* bz    = (const float*)d_in[5];
    const float* Wr    = (const float*)d_in[6];
    const float* Ur    = (const float*)d_in[7];
    const float* br    = (const float*)d_in[8];
    const float* Wh    = (const float*)d_in[9];
    const float* Uh    = (const float*)d_in[10];
    const float* bh    = (const float*)d_in[11];
    const float* alpha = (const float*)d_in[12];
    const float* eta   = (const float*)d_in[13];
    const float* Wo    = (const float*)d_in[14];
    const float* bo    = (const float*)d_in[15];
    const int*   seed  = (const int*)d_in[16];
    float* out = (float*)d_out;

    float* out_output = out;
    float* out_action = out + (size_t)T_STEPS * OUT_DIM;
    float* out_hT     = out_action + T_STEPS;
    float* out_hebb   = out_hT + H_DIM;

    cudaFuncSetAttribute(scan_kernel,
                         cudaFuncAttributeMaxDynamicSharedMemorySize,
                         SCAN_SMEM_BYTES);

    init_kernel<<<(H_DIM + 255) / 256, 256>>>(h0);

    dim3 gtr(H_DIM / 32, H_DIM / 32, 4);
    transpose_kernel<<<gtr, dim3(32, 8)>>>(Uz, Ur, Uh, alpha);

    dim3 gproj(H_DIM / 64, T_STEPS / 64, 3);
    xproj_kernel<<<gproj, 256>>>(x, Wz, bz, Wr, br, Wh, bh);

    scan_kernel<<<NCTA, TPB, SCAN_SMEM_BYTES>>>(hebb0, eta, out_hT, out_hebb);

    out_gemm_kernel<<<T_STEPS, 256>>>(Wo, bo, out_output);

    action_kernel<<<(T_STEPS + 255) / 256, 256>>>(out_output, out_action, seed);
}